// round 1
// baseline (speedup 1.0000x reference)
#include <cuda_runtime.h>
#include <cuda_bf16.h>

// CustomConv2d: out[b,o,h,w] = bias[o] + sum_{c,i,j} xp[b,c,h+i-1,w+j-1]^e[o,c,i,j] * w[o,c,i,j]
// Shapes: x[16,32,64,64] f32, weight[32,32,3,3], bias[32], exponent[32,32,3,3], out[16,32,64,64]
//
// Strategy: x^e = exp2(e * log2(x)); log2 computed once per input element per tile
// (into smem), one MUFU.EX2 per term (604M total -> MUFU-bound floor ~255K cyc/SM).

#define CIN   32
#define COUT  32
#define Hd    64
#define Wd    64
#define TS    16          // spatial tile (both dims)
#define HALO  (TS + 2)    // 18
#define RS    19          // padded row stride in floats (conflict mitigation)
#define OCG   8           // output channels per block

__device__ __forceinline__ float f_lg2(float x) {
    float y; asm("lg2.approx.f32 %0, %1;" : "=f"(y) : "f"(x)); return y;
}
__device__ __forceinline__ float f_ex2(float x) {
    float y; asm("ex2.approx.f32 %0, %1;" : "=f"(y) : "f"(x)); return y;
}

__global__ __launch_bounds__(256, 3)
void conv_pow_kernel(const float* __restrict__ x,
                     const float* __restrict__ weight,
                     const float* __restrict__ bias,
                     const float* __restrict__ expo,
                     float* __restrict__ out) {
    __shared__ float sL[CIN * HALO * RS];   // 32*18*19*4 = 43776 B

    const int tw  = blockIdx.x;             // 0..3 (w tiles)
    const int th  = blockIdx.y;             // 0..3 (h tiles)
    const int bz  = blockIdx.z;             // b*4 + ocg, 0..63
    const int b   = bz >> 2;
    const int ocg = bz & 3;

    const int h0 = th * TS;
    const int w0 = tw * TS;

    // --- Fill smem with log2 of the (haloed) input tile for all 32 channels ---
    const float* xb = x + (size_t)b * (CIN * Hd * Wd);
    for (int idx = threadIdx.x; idx < CIN * HALO * HALO; idx += 256) {
        int c  = idx / (HALO * HALO);
        int rm = idx - c * (HALO * HALO);
        int r  = rm / HALO;
        int cc = rm - r * HALO;
        int gh = h0 - 1 + r;
        int gw = w0 - 1 + cc;
        float v = -1e30f;                    // padding -> exp2(e*v)=0 (and 0^0=1 via e*v=0... e>0 anyway)
        if (gh >= 0 && gh < Hd && gw >= 0 && gw < Wd) {
            v = f_lg2(__ldg(xb + c * (Hd * Wd) + gh * Wd + gw));
        }
        sL[c * (HALO * RS) + r * RS + cc] = v;
    }
    __syncthreads();

    // --- Thread mapping: warp = one oc; lane -> (row, half-row of 8 pixels) ---
    const int oc_l = threadIdx.x >> 5;       // 0..7
    const int pxg  = threadIdx.x & 31;       // 0..31
    const int r    = pxg >> 1;               // 0..15
    const int wb   = (pxg & 1) * 8;          // 0 or 8

    const int oc = ocg * OCG + oc_l;
    const float* __restrict__ Eoc = expo   + oc * (CIN * 9);
    const float* __restrict__ Woc = weight + oc * (CIN * 9);

    float acc[8];
    #pragma unroll
    for (int p = 0; p < 8; p++) acc[p] = 0.0f;

    for (int c = 0; c < CIN; c++) {
        const float* sc = sL + c * (HALO * RS) + r * RS + wb;
        float lx[3][10];
        #pragma unroll
        for (int i = 0; i < 3; i++) {
            #pragma unroll
            for (int k = 0; k < 10; k++)
                lx[i][k] = sc[i * RS + k];
        }
        const float* Ec = Eoc + c * 9;
        const float* Wc = Woc + c * 9;
        #pragma unroll
        for (int i = 0; i < 3; i++) {
            #pragma unroll
            for (int j = 0; j < 3; j++) {
                const float e = __ldg(Ec + i * 3 + j);   // warp-uniform broadcast, L1-hot
                const float w = __ldg(Wc + i * 3 + j);
                #pragma unroll
                for (int p = 0; p < 8; p++) {
                    acc[p] += f_ex2(e * lx[i][j + p]) * w;
                }
            }
        }
    }

    const float bb = __ldg(bias + oc);
    float* ob = out + (((size_t)b * COUT + oc) * Hd + (h0 + r)) * Wd + w0 + wb;
    float4 v0 = make_float4(acc[0] + bb, acc[1] + bb, acc[2] + bb, acc[3] + bb);
    float4 v1 = make_float4(acc[4] + bb, acc[5] + bb, acc[6] + bb, acc[7] + bb);
    reinterpret_cast<float4*>(ob)[0] = v0;
    reinterpret_cast<float4*>(ob)[1] = v1;
}

extern "C" void kernel_launch(void* const* d_in, const int* in_sizes, int n_in,
                              void* d_out, int out_size) {
    const float* x      = (const float*)d_in[0];
    const float* weight = (const float*)d_in[1];
    const float* bias   = (const float*)d_in[2];
    const float* expo   = (const float*)d_in[3];
    float* out          = (float*)d_out;

    dim3 grid(Wd / TS, Hd / TS, 16 * (COUT / OCG));   // 4 x 4 x 64
    conv_pow_kernel<<<grid, 256>>>(x, weight, bias, expo, out);
}

// round 2
// speedup vs baseline: 1.0253x; 1.0253x over previous
#include <cuda_runtime.h>
#include <cuda_bf16.h>

// CustomConv2d: out[b,o,h,w] = bias[o] + sum_{c,i,j} xp[b,c,h+i-1,w+j-1]^e[o,c,i,j] * w[o,c,i,j]
// x[16,32,64,64] f32, weight[32,32,3,3], bias[32], exponent[32,32,3,3], out[16,32,64,64]
//
// x^e = exp2(e * log2(x)); log2 once per input element per tile (smem),
// one MUFU.EX2 per term. MUFU-bound floor = 604M/(148*16) = 255K cycles.
// R2: 8x16 tiles (tail/2), row-window regs, marching pointers (ALU down),
// RS=21 conflict-free LDS, 64-reg cap for 4 blocks/SM.

#define CIN   32
#define COUT  32
#define Hd    64
#define Wd    64
#define TSH   8
#define TSW   16
#define HH    (TSH + 2)    // 10
#define HW    (TSW + 2)    // 18
#define RS    21           // row stride in smem; RS%4==1 -> conflict-free lane map

__device__ __forceinline__ float f_lg2(float x) {
    float y; asm("lg2.approx.f32 %0, %1;" : "=f"(y) : "f"(x)); return y;
}
__device__ __forceinline__ float f_ex2(float x) {
    float y; asm("ex2.approx.f32 %0, %1;" : "=f"(y) : "f"(x)); return y;
}

__global__ __launch_bounds__(256, 4)
void conv_pow_kernel(const float* __restrict__ x,
                     const float* __restrict__ weight,
                     const float* __restrict__ bias,
                     const float* __restrict__ expo,
                     float* __restrict__ out) {
    __shared__ float sL[CIN * HH * RS];   // 32*10*21*4 = 26880 B

    const int tw  = blockIdx.x;            // 0..3  (w tiles of 16)
    const int th  = blockIdx.y;            // 0..7  (h tiles of 8)
    const int bz  = blockIdx.z;            // b*4 + ocg
    const int b   = bz >> 2;
    const int ocg = bz & 3;

    const int h0 = th * TSH;
    const int w0 = tw * TSW;

    // ---- fill smem with log2(x) over the haloed tile, all channels ----
    const float* xb = x + (size_t)b * (CIN * Hd * Wd);
    for (int idx = threadIdx.x; idx < CIN * HH * HW; idx += 256) {
        int c  = idx / (HH * HW);
        int rm = idx - c * (HH * HW);
        int r  = rm / HW;
        int cc = rm - r * HW;
        int gh = h0 - 1 + r;
        int gw = w0 - 1 + cc;
        float v = -1e30f;                    // pad: exp2(e * -1e30) = 0 = 0^e
        if (gh >= 0 && gh < Hd && gw >= 0 && gw < Wd) {
            v = f_lg2(__ldg(xb + c * (Hd * Wd) + gh * Wd + gw));
        }
        sL[c * (HH * RS) + r * RS + cc] = v;
    }
    __syncthreads();

    // ---- warp = one oc; lane -> (row 0..7, 4-px column group) ----
    const int oc_l = threadIdx.x >> 5;       // 0..7
    const int lane = threadIdx.x & 31;
    const int r    = lane >> 2;              // 0..7
    const int wq   = (lane & 3) * 4;         // 0,4,8,12

    const int oc = ocg * 8 + oc_l;
    const float* __restrict__ Ep = expo   + oc * (CIN * 9);
    const float* __restrict__ Wp = weight + oc * (CIN * 9);
    const float* scol = sL + r * RS + wq;

    float a0 = 0.f, a1 = 0.f, a2 = 0.f, a3 = 0.f;

    #pragma unroll 1
    for (int c = 0; c < CIN; c++) {
        const float* sc = scol;
        scol += HH * RS;
        #pragma unroll
        for (int i = 0; i < 3; i++) {
            float l0 = sc[0], l1 = sc[1], l2 = sc[2],
                  l3 = sc[3], l4 = sc[4], l5 = sc[5];
            sc += RS;
            const float e0 = __ldg(Ep + i * 3 + 0);
            const float e1 = __ldg(Ep + i * 3 + 1);
            const float e2 = __ldg(Ep + i * 3 + 2);
            const float w0_ = __ldg(Wp + i * 3 + 0);
            const float w1_ = __ldg(Wp + i * 3 + 1);
            const float w2_ = __ldg(Wp + i * 3 + 2);

            a0 += f_ex2(e0 * l0) * w0_;
            a1 += f_ex2(e0 * l1) * w0_;
            a2 += f_ex2(e0 * l2) * w0_;
            a3 += f_ex2(e0 * l3) * w0_;

            a0 += f_ex2(e1 * l1) * w1_;
            a1 += f_ex2(e1 * l2) * w1_;
            a2 += f_ex2(e1 * l3) * w1_;
            a3 += f_ex2(e1 * l4) * w1_;

            a0 += f_ex2(e2 * l2) * w2_;
            a1 += f_ex2(e2 * l3) * w2_;
            a2 += f_ex2(e2 * l4) * w2_;
            a3 += f_ex2(e2 * l5) * w2_;
        }
        Ep += 9;
        Wp += 9;
    }

    const float bb = __ldg(bias + oc);
    float* ob = out + (((size_t)b * COUT + oc) * Hd + (h0 + r)) * Wd + w0 + wq;
    float4 v = make_float4(a0 + bb, a1 + bb, a2 + bb, a3 + bb);
    *reinterpret_cast<float4*>(ob) = v;
}

extern "C" void kernel_launch(void* const* d_in, const int* in_sizes, int n_in,
                              void* d_out, int out_size) {
    const float* x      = (const float*)d_in[0];
    const float* weight = (const float*)d_in[1];
    const float* bias   = (const float*)d_in[2];
    const float* expo   = (const float*)d_in[3];
    float* out          = (float*)d_out;

    dim3 grid(Wd / TSW, Hd / TSH, 16 * (COUT / 8));   // 4 x 8 x 64 = 2048
    conv_pow_kernel<<<grid, 256>>>(x, weight, bias, expo, out);
}